// round 2
// baseline (speedup 1.0000x reference)
#include <cuda_runtime.h>
#include <math.h>

// Problem constants
constexpr int B_  = 4;
constexpr int N_  = 1024;
constexpr int D_  = 256;
constexpr int H_  = 4;
constexpr int L_  = 2;
constexpr int DK_ = 64;
constexpr int BN_ = B_ * N_;        // 4096
constexpr int FD_ = D_ * H_ * L_;   // 2048

// Scratch (static device globals; no allocations allowed)
__device__ float g_q[BN_ * D_];                 // 4 MB
__device__ float g_k[BN_ * D_];                 // 4 MB
__device__ float g_attn[B_ * H_ * N_ * N_];     // 64 MB (scores -> weights in place)
__device__ float g_denom[B_ * H_ * N_];         // 64 KB
__device__ float g_tmp[H_ * B_ * N_ * D_];      // 16 MB  (Ax + X per (b,h))
__device__ float g_final[BN_ * FD_];            // 32 MB  (concat of all head/layer outputs)

// ---------------------------------------------------------------------------
// Tiled fp32 GEMM cores: 128x128 C tile, K-step 8, 256 threads, 8x8 per thread
// ---------------------------------------------------------------------------
constexpr int TBM = 128, TBN = 128, TBK = 8;

__device__ __forceinline__ void gemm_nn_core(const float* __restrict__ A, int lda,
                                             const float* __restrict__ Bm, int ldb,
                                             int K, float acc[8][8]) {
    __shared__ float As[TBK][TBM];
    __shared__ float Bs[TBK][TBN];
    const int tid = threadIdx.x;
    const int tx = tid & 15, ty = tid >> 4;
    const int arow = tid >> 1;          // 0..127
    const int akb  = (tid & 1) * 4;     // 0 or 4
    const int bkr  = tid >> 5;          // 0..7
    const int bnb  = (tid & 31) * 4;    // 0..124

    for (int k0 = 0; k0 < K; k0 += TBK) {
        float4 av = *reinterpret_cast<const float4*>(A + (size_t)arow * lda + k0 + akb);
        As[akb + 0][arow] = av.x;
        As[akb + 1][arow] = av.y;
        As[akb + 2][arow] = av.z;
        As[akb + 3][arow] = av.w;
        float4 bv = *reinterpret_cast<const float4*>(Bm + (size_t)(k0 + bkr) * ldb + bnb);
        *reinterpret_cast<float4*>(&Bs[bkr][bnb]) = bv;
        __syncthreads();
#pragma unroll
        for (int kk = 0; kk < TBK; kk++) {
            float ra[8], rb[8];
#pragma unroll
            for (int i = 0; i < 8; i++) ra[i] = As[kk][ty * 8 + i];
#pragma unroll
            for (int j = 0; j < 8; j++) rb[j] = Bs[kk][tx * 8 + j];
#pragma unroll
            for (int i = 0; i < 8; i++)
#pragma unroll
                for (int j = 0; j < 8; j++)
                    acc[i][j] = fmaf(ra[i], rb[j], acc[i][j]);
        }
        __syncthreads();
    }
}

// C = A @ B^T : B is [Nc, K] row-major (load Bs[k][n] = B[n][k])
__device__ __forceinline__ void gemm_nt_core(const float* __restrict__ A, int lda,
                                             const float* __restrict__ Bm, int ldb,
                                             int K, float acc[8][8]) {
    __shared__ float As[TBK][TBM];
    __shared__ float Bs[TBK][TBN];
    const int tid = threadIdx.x;
    const int tx = tid & 15, ty = tid >> 4;
    const int arow = tid >> 1;
    const int akb  = (tid & 1) * 4;

    for (int k0 = 0; k0 < K; k0 += TBK) {
        float4 av = *reinterpret_cast<const float4*>(A + (size_t)arow * lda + k0 + akb);
        As[akb + 0][arow] = av.x;
        As[akb + 1][arow] = av.y;
        As[akb + 2][arow] = av.z;
        As[akb + 3][arow] = av.w;
        float4 bv = *reinterpret_cast<const float4*>(Bm + (size_t)arow * ldb + k0 + akb);
        Bs[akb + 0][arow] = bv.x;
        Bs[akb + 1][arow] = bv.y;
        Bs[akb + 2][arow] = bv.z;
        Bs[akb + 3][arow] = bv.w;
        __syncthreads();
#pragma unroll
        for (int kk = 0; kk < TBK; kk++) {
            float ra[8], rb[8];
#pragma unroll
            for (int i = 0; i < 8; i++) ra[i] = As[kk][ty * 8 + i];
#pragma unroll
            for (int j = 0; j < 8; j++) rb[j] = Bs[kk][tx * 8 + j];
#pragma unroll
            for (int i = 0; i < 8; i++)
#pragma unroll
                for (int j = 0; j < 8; j++)
                    acc[i][j] = fmaf(ra[i], rb[j], acc[i][j]);
        }
        __syncthreads();
    }
}

// ---------------------------------------------------------------------------
// Kernel 1: projections.  C[4096,256] = A[4096,256] @ W[256,256] (+bias) (+=)
// dst: 0 -> g_q, 1 -> g_k
// ---------------------------------------------------------------------------
__global__ __launch_bounds__(256) void proj_kernel(const float* __restrict__ A,
                                                   const float* __restrict__ W,
                                                   const float* __restrict__ bias,
                                                   int dst, int accum) {
    float acc[8][8] = {};
    const float* Ap = A + (size_t)blockIdx.y * 128 * D_;
    const float* Wp = W + blockIdx.x * 128;
    gemm_nn_core(Ap, D_, Wp, D_, D_, acc);
    float* C = dst ? g_k : g_q;
    const int tx = threadIdx.x & 15, ty = threadIdx.x >> 4;
    const int m0 = blockIdx.y * 128 + ty * 8;
    const int n0 = blockIdx.x * 128 + tx * 8;
#pragma unroll
    for (int i = 0; i < 8; i++)
#pragma unroll
        for (int j = 0; j < 8; j++) {
            float v = acc[i][j];
            if (bias) v += bias[n0 + j];
            float* cp = &C[(size_t)(m0 + i) * D_ + n0 + j];
            if (accum) *cp += v; else *cp = v;
        }
}

// ---------------------------------------------------------------------------
// Kernel 2: scores[bh] = q_h @ k_h^T   (K = 64)
// grid (8, 8, 16)
// ---------------------------------------------------------------------------
__global__ __launch_bounds__(256) void scores_kernel() {
    const int bh = blockIdx.z;
    const int b = bh >> 2, h = bh & 3;
    const float* Ap = g_q + (size_t)b * N_ * D_ + h * DK_ + (size_t)blockIdx.y * 128 * D_;
    const float* Bp = g_k + (size_t)b * N_ * D_ + h * DK_ + (size_t)blockIdx.x * 128 * D_;
    float acc[8][8] = {};
    gemm_nt_core(Ap, D_, Bp, D_, DK_, acc);
    float* C = g_attn + (size_t)bh * N_ * N_;
    const int tx = threadIdx.x & 15, ty = threadIdx.x >> 4;
    const int m0 = blockIdx.y * 128 + ty * 8;
    const int n0 = blockIdx.x * 128 + tx * 8;
#pragma unroll
    for (int i = 0; i < 8; i++)
#pragma unroll
        for (int j = 0; j < 8; j++)
            C[(size_t)(m0 + i) * N_ + n0 + j] = acc[i][j];
}

// ---------------------------------------------------------------------------
// Kernel 3: z-score attention (in-place on g_attn) + per-row denom
// one block per (b,h,i) row; 256 threads, 4 elements each
// ---------------------------------------------------------------------------
__device__ __forceinline__ float blockReduceSum(float v, float* sbuf) {
    const int tid = threadIdx.x;
#pragma unroll
    for (int o = 16; o > 0; o >>= 1) v += __shfl_xor_sync(0xffffffffu, v, o);
    if ((tid & 31) == 0) sbuf[tid >> 5] = v;
    __syncthreads();
    if (tid < 8) {
        v = sbuf[tid];
#pragma unroll
        for (int o = 4; o > 0; o >>= 1) v += __shfl_xor_sync(0xffu, v, o);
        if (tid == 0) sbuf[0] = v;
    }
    __syncthreads();
    float r = sbuf[0];
    __syncthreads();
    return r;
}

__device__ __forceinline__ float blockReduceMax(float v, float* sbuf) {
    const int tid = threadIdx.x;
#pragma unroll
    for (int o = 16; o > 0; o >>= 1) v = fmaxf(v, __shfl_xor_sync(0xffffffffu, v, o));
    if ((tid & 31) == 0) sbuf[tid >> 5] = v;
    __syncthreads();
    if (tid < 8) {
        v = sbuf[tid];
#pragma unroll
        for (int o = 4; o > 0; o >>= 1) v = fmaxf(v, __shfl_xor_sync(0xffu, v, o));
        if (tid == 0) sbuf[0] = v;
    }
    __syncthreads();
    float r = sbuf[0];
    __syncthreads();
    return r;
}

__global__ __launch_bounds__(256) void zscore_kernel(const int* __restrict__ mask,
                                                     const int* __restrict__ adj) {
    const int row = blockIdx.x;          // 0 .. B*H*N-1
    const int i  = row & (N_ - 1);
    const int bh = row >> 10;
    const int b  = bh >> 2;
    float* sc = g_attn + (size_t)row * N_;
    const int* adjrow = adj + ((size_t)b * N_ + i) * N_;
    const int* mrow = mask + (size_t)b * N_;
    const int tid = threadIdx.x;
    __shared__ float sbuf[8];

    float v[4], av[4];
    int mv[4];
    float cnt = 0.f, s = 0.f;
#pragma unroll
    for (int e = 0; e < 4; e++) {
        int j = tid + e * 256;
        v[e] = sc[j];
        mv[e] = (mrow[j] == 0);
        av[e] = (float)adjrow[j];
        if (mv[e]) { cnt += 1.f; s += v[e]; }
    }
    cnt = blockReduceSum(cnt, sbuf);
    s   = blockReduceSum(s, sbuf);
    const float mean = s / (cnt + 1e-4f);

    float ss = 0.f;
#pragma unroll
    for (int e = 0; e < 4; e++) {
        float d = v[e] - mean;
        if (mv[e]) ss += d * d;
    }
    ss = blockReduceSum(ss, sbuf);
    const float stdv = sqrtf(ss / (cnt + 1e-4f) + 1e-10f);

    float s2[4];
    int keep[4];
#pragma unroll
    for (int e = 0; e < 4; e++) {
        float z = (v[e] - mean) / (stdv + 1e-4f);
        if (!mv[e]) z = 0.f;
        int th = (z < 0.f);
        s2[e] = (th || !mv[e]) ? -1e9f : z;
        keep[e] = (mv[e] && !th && (av[e] != 0.f));
    }
    float mx = -1e30f;
#pragma unroll
    for (int e = 0; e < 4; e++) mx = fmaxf(mx, s2[e]);
    mx = blockReduceMax(mx, sbuf);

    float ev[4], se = 0.f;
#pragma unroll
    for (int e = 0; e < 4; e++) {
        float ee = mv[e] ? (expf(s2[e] - mx) * av[e]) : 0.f;
        ee += 1e-10f;
        ev[e] = ee;
        se += ee;
    }
    se = blockReduceSum(se, sbuf);

    float dsum = 0.f;
#pragma unroll
    for (int e = 0; e < 4; e++) {
        int j = tid + e * 256;
        float w = keep[e] ? (ev[e] / se) : 0.f;
        sc[j] = w;
        dsum += w;
    }
    dsum = blockReduceSum(dsum, sbuf);
    if (tid == 0) g_denom[row] = dsum + 1.f;
}

// ---------------------------------------------------------------------------
// Kernel 4: T[bh] = a[bh] @ X[b]  +  X[b]        (K = 1024)
// l==0: X = gcn_inputs (ld D);  l==1: X = g_final col slice 2*h*D (ld FD)
// grid (2, 8, 16)
// ---------------------------------------------------------------------------
__global__ __launch_bounds__(256) void axpx_kernel(const float* __restrict__ gcn, int l) {
    const int bh = blockIdx.z;
    const int b = bh >> 2, h = bh & 3;
    const float* Ap = g_attn + (size_t)bh * N_ * N_ + (size_t)blockIdx.y * 128 * N_;
    const float* X;
    int ldx;
    if (l == 0) { X = gcn + (size_t)b * N_ * D_; ldx = D_; }
    else        { X = g_final + (size_t)b * N_ * FD_ + (2 * h) * D_; ldx = FD_; }
    const float* Bp = X + blockIdx.x * 128;
    float acc[8][8] = {};
    gemm_nn_core(Ap, N_, Bp, ldx, N_, acc);
    float* C = g_tmp + (size_t)bh * N_ * D_;
    const int tx = threadIdx.x & 15, ty = threadIdx.x >> 4;
    const int m0 = blockIdx.y * 128 + ty * 8;
    const int n0 = blockIdx.x * 128 + tx * 8;
#pragma unroll
    for (int i = 0; i < 8; i++)
#pragma unroll
        for (int j = 0; j < 8; j++)
            C[(size_t)(m0 + i) * D_ + n0 + j] =
                acc[i][j] + X[(size_t)(m0 + i) * ldx + n0 + j];
}

// ---------------------------------------------------------------------------
// Kernel 5: final[:, idx*D : ] = relu((T[bh] @ W_gcn[idx] + 2*b_gcn[idx]) / denom)
// grid (2, 8, 16)
// ---------------------------------------------------------------------------
__global__ __launch_bounds__(256) void tw_kernel(const float* __restrict__ Wg,
                                                 const float* __restrict__ bg, int l) {
    const int bh = blockIdx.z;
    const int b = bh >> 2, h = bh & 3;
    const int idx = h * L_ + l;
    const float* Ap = g_tmp + (size_t)bh * N_ * D_ + (size_t)blockIdx.y * 128 * D_;
    const float* Wp = Wg + (size_t)idx * D_ * D_ + blockIdx.x * 128;
    float acc[8][8] = {};
    gemm_nn_core(Ap, D_, Wp, D_, D_, acc);
    float* C = g_final + (size_t)b * N_ * FD_ + (size_t)idx * D_;
    const float* dn = g_denom + (size_t)bh * N_;
    const float* bgp = bg + (size_t)idx * D_;
    const int tx = threadIdx.x & 15, ty = threadIdx.x >> 4;
    const int m0 = blockIdx.y * 128 + ty * 8;
    const int n0 = blockIdx.x * 128 + tx * 8;
#pragma unroll
    for (int i = 0; i < 8; i++) {
        const float inv = 1.f / dn[m0 + i];
#pragma unroll
        for (int j = 0; j < 8; j++) {
            float vv = (acc[i][j] + 2.f * bgp[n0 + j]) * inv;
            C[(size_t)(m0 + i) * FD_ + n0 + j] = fmaxf(vv, 0.f);
        }
    }
}

// ---------------------------------------------------------------------------
// Kernel 6: out = gcn_inputs + g_final @ W_out + b_out   (K = 2048)
// grid (2, 32)
// ---------------------------------------------------------------------------
__global__ __launch_bounds__(256) void final_kernel(const float* __restrict__ gcn,
                                                    const float* __restrict__ Wo,
                                                    const float* __restrict__ bo,
                                                    float* __restrict__ out) {
    const float* Ap = g_final + (size_t)blockIdx.y * 128 * FD_;
    const float* Wp = Wo + blockIdx.x * 128;
    float acc[8][8] = {};
    gemm_nn_core(Ap, FD_, Wp, D_, FD_, acc);
    const int tx = threadIdx.x & 15, ty = threadIdx.x >> 4;
    const int m0 = blockIdx.y * 128 + ty * 8;
    const int n0 = blockIdx.x * 128 + tx * 8;
#pragma unroll
    for (int i = 0; i < 8; i++)
#pragma unroll
        for (int j = 0; j < 8; j++)
            out[(size_t)(m0 + i) * D_ + n0 + j] =
                gcn[(size_t)(m0 + i) * D_ + n0 + j] + acc[i][j] + bo[n0 + j];
}

// ---------------------------------------------------------------------------
extern "C" void kernel_launch(void* const* d_in, const int* in_sizes, int n_in,
                              void* d_out, int out_size) {
    const float* gcn   = (const float*)d_in[0];
    const float* rel   = (const float*)d_in[1];
    const int*   adj   = (const int*)d_in[2];
    const int*   mask  = (const int*)d_in[3];
    const float* W_Q   = (const float*)d_in[4];
    const float* b_Q   = (const float*)d_in[5];
    const float* W_K   = (const float*)d_in[6];
    const float* b_K   = (const float*)d_in[7];
    const float* W_gcn = (const float*)d_in[8];
    const float* b_gcn = (const float*)d_in[9];
    const float* W_out = (const float*)d_in[10];
    const float* b_out = (const float*)d_in[11];
    float* out = (float*)d_out;

    const dim3 thr(256);

    // q = [gcn | rel] @ W_Q + b_Q   (split the K=512 GEMM into two K=256 GEMMs)
    proj_kernel<<<dim3(2, 32), thr>>>(gcn, W_Q,              b_Q, /*dst=*/0, /*accum=*/0);
    proj_kernel<<<dim3(2, 32), thr>>>(rel, W_Q + 256 * 256,  nullptr, 0,     1);
    // k = gcn @ W_K + b_K
    proj_kernel<<<dim3(2, 32), thr>>>(gcn, W_K,              b_K, 1,         0);

    // scores per (b,h)
    scores_kernel<<<dim3(8, 8, 16), thr>>>();

    // z-score attention -> weights (in place) + denom
    zscore_kernel<<<B_ * H_ * N_, thr>>>(mask, adj);

    // GCN layers (all heads batched per layer)
    for (int l = 0; l < L_; l++) {
        axpx_kernel<<<dim3(2, 8, 16), thr>>>(gcn, l);
        tw_kernel<<<dim3(2, 8, 16), thr>>>(W_gcn, b_gcn, l);
    }

    // residual + output projection
    final_kernel<<<dim3(2, 32), thr>>>(gcn, W_out, b_out, out);
}

// round 4
// speedup vs baseline: 2.3087x; 2.3087x over previous
#include <cuda_runtime.h>
#include <cstdint>
#include <math.h>

// Problem constants
constexpr int B_  = 4;
constexpr int N_  = 1024;
constexpr int D_  = 256;
constexpr int H_  = 4;
constexpr int L_  = 2;
constexpr int DK_ = 64;
constexpr int BN_ = B_ * N_;        // 4096
constexpr int FD_ = D_ * H_ * L_;   // 2048

// Scratch (static device globals)
__device__ float g_q[BN_ * D_];                 // 4 MB
__device__ float g_k[BN_ * D_];                 // 4 MB
__device__ float g_attn[16 * N_ * N_];          // 64 MB
__device__ float g_denom[16 * N_];              // 64 KB
__device__ float g_tmp[16 * N_ * D_];           // 16 MB
__device__ float g_final[BN_ * FD_];            // 32 MB

// ===========================================================================
// mma.sync tf32 GEMM core
//   block tile 128(M) x 128(N), K-chunk 32, 256 threads = 8 warps (4m x 2n)
//   warp tile 32(M) x 64(N) built from m16n8k8 tf32 mma
// ===========================================================================
constexpr int AS_STR = 36;    // A row stride (floats): bank = 4*row + k (conflict-free)
constexpr int BS_STR = 136;   // B row stride (floats): bank = 8*k + n (conflict-free)

__device__ __forceinline__ uint32_t f2tf(float x) {
    uint32_t r;
    asm("cvt.rna.tf32.f32 %0, %1;" : "=r"(r) : "f"(x));
    return r;
}

__device__ __forceinline__ void mma16n8k8(float d[4], const uint32_t a[4],
                                          const uint32_t b[2]) {
    asm volatile(
        "mma.sync.aligned.m16n8k8.row.col.f32.tf32.tf32.f32 "
        "{%0,%1,%2,%3}, {%4,%5,%6,%7}, {%8,%9}, {%0,%1,%2,%3};"
        : "+f"(d[0]), "+f"(d[1]), "+f"(d[2]), "+f"(d[3])
        : "r"(a[0]), "r"(a[1]), "r"(a[2]), "r"(a[3]), "r"(b[0]), "r"(b[1]));
}

// A: [>=128 rows, lda] row-major (pre-offset to block row / col 0 of K)
// B: [K rows, ldb] row-major (pre-offset to block col)
__device__ __forceinline__ void mma_core(const float* __restrict__ A, int lda,
                                         const float* __restrict__ B, int ldb,
                                         int K, float c[2][8][4]) {
    __shared__ uint32_t As[128 * AS_STR];
    __shared__ uint32_t Bs[32 * BS_STR];

    const int tid = threadIdx.x;
    const int lane = tid & 31, wid = tid >> 5;
    const int wm = (wid >> 1) * 32;   // warp row base
    const int wn = (wid & 1) * 64;    // warp col base
    const int qr = lane >> 2, qk = lane & 3;

    // staging indices
    const int arow = tid >> 3, ac4 = tid & 7;     // A: rows arow+32e, float4 col ac4
    const int bk   = tid >> 5, bc4 = tid & 31;    // B: k-rows bk+8e, float4 col bc4

    float4 pa[4], pb[4];
    const int niter = K >> 5;

    // prologue load chunk 0
#pragma unroll
    for (int e = 0; e < 4; e++)
        pa[e] = *(const float4*)(A + (size_t)(arow + 32 * e) * lda + ac4 * 4);
#pragma unroll
    for (int e = 0; e < 4; e++)
        pb[e] = *(const float4*)(B + (size_t)(bk + 8 * e) * ldb + bc4 * 4);

    for (int kt = 0; kt < niter; kt++) {
        // store staged chunk to SMEM (convert to tf32)
#pragma unroll
        for (int e = 0; e < 4; e++) {
            uint4 t = make_uint4(f2tf(pa[e].x), f2tf(pa[e].y), f2tf(pa[e].z), f2tf(pa[e].w));
            *(uint4*)&As[(arow + 32 * e) * AS_STR + ac4 * 4] = t;
        }
#pragma unroll
        for (int e = 0; e < 4; e++) {
            uint4 t = make_uint4(f2tf(pb[e].x), f2tf(pb[e].y), f2tf(pb[e].z), f2tf(pb[e].w));
            *(uint4*)&Bs[(bk + 8 * e) * BS_STR + bc4 * 4] = t;
        }
        __syncthreads();

        // prefetch next chunk (overlaps with compute below)
        if (kt + 1 < niter) {
            const int k0 = (kt + 1) << 5;
#pragma unroll
            for (int e = 0; e < 4; e++)
                pa[e] = *(const float4*)(A + (size_t)(arow + 32 * e) * lda + k0 + ac4 * 4);
#pragma unroll
            for (int e = 0; e < 4; e++)
                pb[e] = *(const float4*)(B + (size_t)(k0 + bk + 8 * e) * ldb + bc4 * 4);
        }

        // compute 4 k8-steps from SMEM
#pragma unroll
        for (int kk = 0; kk < 4; kk++) {
            const int k0 = kk * 8;
            uint32_t af[2][4];
#pragma unroll
            for (int mi = 0; mi < 2; mi++) {
                const int rb = wm + mi * 16 + qr;
                af[mi][0] = As[(rb)     * AS_STR + k0 + qk];
                af[mi][1] = As[(rb + 8) * AS_STR + k0 + qk];
                af[mi][2] = As[(rb)     * AS_STR + k0 + qk + 4];
                af[mi][3] = As[(rb + 8) * AS_STR + k0 + qk + 4];
            }
#pragma unroll
            for (int ni = 0; ni < 8; ni++) {
                uint32_t bf[2];
                bf[0] = Bs[(k0 + qk)     * BS_STR + wn + ni * 8 + qr];
                bf[1] = Bs[(k0 + qk + 4) * BS_STR + wn + ni * 8 + qr];
                mma16n8k8(c[0][ni], af[0], bf);
                mma16n8k8(c[1][ni], af[1], bf);
            }
        }
        __syncthreads();
    }
}

// Epilogue index helper: element (mi, half, ni, j) ->
//   row = wm + mi*16 + qr + half*8 ;  col = wn + ni*8 + 2*qk + j
#define EPILOGUE_LOOP(BODY)                                                   \
    do {                                                                      \
        const int lane = threadIdx.x & 31, wid = threadIdx.x >> 5;            \
        const int wm = (wid >> 1) * 32, wn = (wid & 1) * 64;                  \
        const int qr = lane >> 2, qk = lane & 3;                              \
        _Pragma("unroll")                                                     \
        for (int mi = 0; mi < 2; mi++)                                        \
            _Pragma("unroll")                                                 \
            for (int half = 0; half < 2; half++) {                            \
                const int row = wm + mi * 16 + qr + half * 8;                 \
                _Pragma("unroll")                                             \
                for (int ni = 0; ni < 8; ni++) {                              \
                    const int col = wn + ni * 8 + 2 * qk;                     \
                    float v0 = c[mi][ni][half * 2 + 0];                       \
                    float v1 = c[mi][ni][half * 2 + 1];                       \
                    BODY                                                      \
                }                                                             \
            }                                                                 \
    } while (0)

// ===========================================================================
// Kernel: T[bh] = a[bh] @ X[b] + X[b]   (K = 1024) -> g_tmp
// grid (2 ntiles, 8 mtiles, 16 bh)
// ===========================================================================
__global__ __launch_bounds__(256) void axpx_mma(const float* __restrict__ gcn, int l) {
    const int bh = blockIdx.z, b = bh >> 2, h = bh & 3;
    const int m0 = blockIdx.y * 128, n0 = blockIdx.x * 128;
    const float* A = g_attn + (size_t)bh * N_ * N_ + (size_t)m0 * N_;
    const float* X; int ldx;
    if (l == 0) { X = gcn + (size_t)b * N_ * D_; ldx = D_; }
    else        { X = g_final + (size_t)b * N_ * FD_ + 2 * h * D_; ldx = FD_; }

    float c[2][8][4] = {};
    mma_core(A, N_, X + n0, ldx, N_, c);

    const float* Xe = X + (size_t)m0 * ldx + n0;
    float* C = g_tmp + (size_t)bh * N_ * D_ + (size_t)m0 * D_ + n0;
    EPILOGUE_LOOP({
        v0 += Xe[(size_t)row * ldx + col];
        v1 += Xe[(size_t)row * ldx + col + 1];
        *(float2*)(C + (size_t)row * D_ + col) = make_float2(v0, v1);
    });
}

// ===========================================================================
// Kernel: g_final[:, idx*D:] = relu((T @ W_gcn[idx] + 2*b_gcn[idx]) / denom)
// grid (2 ntiles, 8 mtiles, 16 bh), K = 256
// ===========================================================================
__global__ __launch_bounds__(256) void tw_mma(const float* __restrict__ Wg,
                                              const float* __restrict__ bg, int l) {
    const int bh = blockIdx.z, b = bh >> 2, h = bh & 3;
    const int idx = h * L_ + l;
    const int m0 = blockIdx.y * 128, n0 = blockIdx.x * 128;
    const float* A = g_tmp + (size_t)bh * N_ * D_ + (size_t)m0 * D_;
    const float* Bw = Wg + (size_t)idx * D_ * D_ + n0;

    float c[2][8][4] = {};
    mma_core(A, D_, Bw, D_, D_, c);

    float* C = g_final + (size_t)b * N_ * FD_ + (size_t)idx * D_ + (size_t)m0 * FD_ + n0;
    const float* dn = g_denom + (size_t)bh * N_ + m0;
    const float* bgp = bg + (size_t)idx * D_ + n0;
    EPILOGUE_LOOP({
        const float inv = 1.f / dn[row];
        v0 = fmaxf((v0 + 2.f * bgp[col])     * inv, 0.f);
        v1 = fmaxf((v1 + 2.f * bgp[col + 1]) * inv, 0.f);
        *(float2*)(C + (size_t)row * FD_ + col) = make_float2(v0, v1);
    });
}

// ===========================================================================
// Kernel: out = gcn + g_final @ W_out + b_out   (K = 2048)
// grid (2 ntiles, 32 mtiles)
// ===========================================================================
__global__ __launch_bounds__(256) void final_mma(const float* __restrict__ gcn,
                                                 const float* __restrict__ Wo,
                                                 const float* __restrict__ bo,
                                                 float* __restrict__ out) {
    const int m0 = blockIdx.y * 128, n0 = blockIdx.x * 128;
    const float* A = g_final + (size_t)m0 * FD_;

    float c[2][8][4] = {};
    mma_core(A, FD_, Wo + n0, D_, FD_, c);

    const float* G = gcn + (size_t)m0 * D_ + n0;
    float* C = out + (size_t)m0 * D_ + n0;
    const float* bop = bo + n0;
    EPILOGUE_LOOP({
        v0 += G[(size_t)row * D_ + col]     + bop[col];
        v1 += G[(size_t)row * D_ + col + 1] + bop[col + 1];
        *(float2*)(C + (size_t)row * D_ + col) = make_float2(v0, v1);
    });
}

// ===========================================================================
// FFMA path for q/k/scores (z-score threshold is precision-sensitive)
// ===========================================================================
constexpr int TBK = 8;

__device__ __forceinline__ void gemm_nn_core(const float* __restrict__ A, int lda,
                                             const float* __restrict__ Bm, int ldb,
                                             int K, float acc[8][8]) {
    __shared__ float As[TBK][128];
    __shared__ float Bs[TBK][128];
    const int tid = threadIdx.x;
    const int tx = tid & 15, ty = tid >> 4;
    const int arow = tid >> 1;
    const int akb  = (tid & 1) * 4;
    const int bkr  = tid >> 5;
    const int bnb  = (tid & 31) * 4;
    for (int k0 = 0; k0 < K; k0 += TBK) {
        float4 av = *reinterpret_cast<const float4*>(A + (size_t)arow * lda + k0 + akb);
        As[akb + 0][arow] = av.x; As[akb + 1][arow] = av.y;
        As[akb + 2][arow] = av.z; As[akb + 3][arow] = av.w;
        float4 bv = *reinterpret_cast<const float4*>(Bm + (size_t)(k0 + bkr) * ldb + bnb);
        *reinterpret_cast<float4*>(&Bs[bkr][bnb]) = bv;
        __syncthreads();
#pragma unroll
        for (int kk = 0; kk < TBK; kk++) {
            float ra[8], rb[8];
#pragma unroll
            for (int i = 0; i < 8; i++) ra[i] = As[kk][ty * 8 + i];
#pragma unroll
            for (int j = 0; j < 8; j++) rb[j] = Bs[kk][tx * 8 + j];
#pragma unroll
            for (int i = 0; i < 8; i++)
#pragma unroll
                for (int j = 0; j < 8; j++)
                    acc[i][j] = fmaf(ra[i], rb[j], acc[i][j]);
        }
        __syncthreads();
    }
}

__device__ __forceinline__ void gemm_nt_core(const float* __restrict__ A, int lda,
                                             const float* __restrict__ Bm, int ldb,
                                             int K, float acc[8][8]) {
    __shared__ float As[TBK][128];
    __shared__ float Bs[TBK][128];
    const int tid = threadIdx.x;
    const int tx = tid & 15, ty = tid >> 4;
    const int arow = tid >> 1;
    const int akb  = (tid & 1) * 4;
    for (int k0 = 0; k0 < K; k0 += TBK) {
        float4 av = *reinterpret_cast<const float4*>(A + (size_t)arow * lda + k0 + akb);
        As[akb + 0][arow] = av.x; As[akb + 1][arow] = av.y;
        As[akb + 2][arow] = av.z; As[akb + 3][arow] = av.w;
        float4 bv = *reinterpret_cast<const float4*>(Bm + (size_t)arow * ldb + k0 + akb);
        Bs[akb + 0][arow] = bv.x; Bs[akb + 1][arow] = bv.y;
        Bs[akb + 2][arow] = bv.z; Bs[akb + 3][arow] = bv.w;
        __syncthreads();
#pragma unroll
        for (int kk = 0; kk < TBK; kk++) {
            float ra[8], rb[8];
#pragma unroll
            for (int i = 0; i < 8; i++) ra[i] = As[kk][ty * 8 + i];
#pragma unroll
            for (int j = 0; j < 8; j++) rb[j] = Bs[kk][tx * 8 + j];
#pragma unroll
            for (int i = 0; i < 8; i++)
#pragma unroll
                for (int j = 0; j < 8; j++)
                    acc[i][j] = fmaf(ra[i], rb[j], acc[i][j]);
        }
        __syncthreads();
    }
}

__global__ __launch_bounds__(256) void proj_kernel(const float* __restrict__ A,
                                                   const float* __restrict__ W,
                                                   const float* __restrict__ bias,
                                                   int dst, int accum) {
    float acc[8][8] = {};
    const float* Ap = A + (size_t)blockIdx.y * 128 * D_;
    const float* Wp = W + blockIdx.x * 128;
    gemm_nn_core(Ap, D_, Wp, D_, D_, acc);
    float* C = dst ? g_k : g_q;
    const int tx = threadIdx.x & 15, ty = threadIdx.x >> 4;
    const int m0 = blockIdx.y * 128 + ty * 8;
    const int n0 = blockIdx.x * 128 + tx * 8;
#pragma unroll
    for (int i = 0; i < 8; i++)
#pragma unroll
        for (int j = 0; j < 8; j++) {
            float v = acc[i][j];
            if (bias) v += bias[n0 + j];
            float* cp = &C[(size_t)(m0 + i) * D_ + n0 + j];
            if (accum) *cp += v; else *cp = v;
        }
}

__global__ __launch_bounds__(256) void scores_kernel() {
    const int bh = blockIdx.z;
    const int b = bh >> 2, h = bh & 3;
    const float* Ap = g_q + (size_t)b * N_ * D_ + h * DK_ + (size_t)blockIdx.y * 128 * D_;
    const float* Bp = g_k + (size_t)b * N_ * D_ + h * DK_ + (size_t)blockIdx.x * 128 * D_;
    float acc[8][8] = {};
    gemm_nt_core(Ap, D_, Bp, D_, DK_, acc);
    float* C = g_attn + (size_t)bh * N_ * N_;
    const int tx = threadIdx.x & 15, ty = threadIdx.x >> 4;
    const int m0 = blockIdx.y * 128 + ty * 8;
    const int n0 = blockIdx.x * 128 + tx * 8;
#pragma unroll
    for (int i = 0; i < 8; i++)
#pragma unroll
        for (int j = 0; j < 8; j++)
            C[(size_t)(m0 + i) * N_ + n0 + j] = acc[i][j];
}

// ---------------------------------------------------------------------------
// z-score attention
// ---------------------------------------------------------------------------
__device__ __forceinline__ float blockReduceSum(float v, float* sbuf) {
    const int tid = threadIdx.x;
#pragma unroll
    for (int o = 16; o > 0; o >>= 1) v += __shfl_xor_sync(0xffffffffu, v, o);
    if ((tid & 31) == 0) sbuf[tid >> 5] = v;
    __syncthreads();
    if (tid < 8) {
        v = sbuf[tid];
#pragma unroll
        for (int o = 4; o > 0; o >>= 1) v += __shfl_xor_sync(0xffu, v, o);
        if (tid == 0) sbuf[0] = v;
    }
    __syncthreads();
    float r = sbuf[0];
    __syncthreads();
    return r;
}
__device__ __forceinline__ float blockReduceMax(float v, float* sbuf) {
    const int tid = threadIdx.x;
#pragma unroll
    for (int o = 16; o > 0; o >>= 1) v = fmaxf(v, __shfl_xor_sync(0xffffffffu, v, o));
    if ((tid & 31) == 0) sbuf[tid >> 5] = v;
    __syncthreads();
    if (tid < 8) {
        v = sbuf[tid];
#pragma unroll
        for (int o = 4; o > 0; o >>= 1) v = fmaxf(v, __shfl_xor_sync(0xffu, v, o));
        if (tid == 0) sbuf[0] = v;
    }
    __syncthreads();
    float r = sbuf[0];
    __syncthreads();
    return r;
}

__global__ __launch_bounds__(256) void zscore_kernel(const int* __restrict__ mask,
                                                     const int* __restrict__ adj) {
    const int row = blockIdx.x;
    const int i  = row & (N_ - 1);
    const int bh = row >> 10;
    const int b  = bh >> 2;
    float* sc = g_attn + (size_t)row * N_;
    const int* adjrow = adj + ((size_t)b * N_ + i) * N_;
    const int* mrow = mask + (size_t)b * N_;
    const int tid = threadIdx.x;
    __shared__ float sbuf[8];

    float v[4], av[4];
    int mv[4];
    float cnt = 0.f, s = 0.f;
#pragma unroll
    for (int e = 0; e < 4; e++) {
        int j = tid + e * 256;
        v[e] = sc[j];
        mv[e] = (mrow[j] == 0);
        av[e] = (float)adjrow[j];
        if (mv[e]) { cnt += 1.f; s += v[e]; }
    }
    cnt = blockReduceSum(cnt, sbuf);
    s   = blockReduceSum(s, sbuf);
    const float mean = s / (cnt + 1e-4f);

    float ss = 0.f;
#pragma unroll
    for (int e = 0; e < 4; e++) {
        float d = v[e] - mean;
        if (mv[e]) ss += d * d;
    }
    ss = blockReduceSum(ss, sbuf);
    const float stdv = sqrtf(ss / (cnt + 1e-4f) + 1e-10f);

    float s2[4];
    int keep[4];
#pragma unroll
    for (int e = 0; e < 4; e++) {
        float z = (v[e] - mean) / (stdv + 1e-4f);
        if (!mv[e]) z = 0.f;
        int th = (z < 0.f);
        s2[e] = (th || !mv[e]) ? -1e9f : z;
        keep[e] = (mv[e] && !th && (av[e] != 0.f));
    }
    float mx = -1e30f;
#pragma unroll
    for (int e = 0; e < 4; e++) mx = fmaxf(mx, s2[e]);
    mx = blockReduceMax(mx, sbuf);

    float ev[4], se = 0.f;
#pragma unroll
    for (int e = 0; e < 4; e++) {
        float ee = mv[e] ? (expf(s2[e] - mx) * av[e]) : 0.f;
        ee += 1e-10f;
        ev[e] = ee;
        se += ee;
    }
    se = blockReduceSum(se, sbuf);

    float dsum = 0.f;
#pragma unroll
    for (int e = 0; e < 4; e++) {
        int j = tid + e * 256;
        float w = keep[e] ? (ev[e] / se) : 0.f;
        sc[j] = w;
        dsum += w;
    }
    dsum = blockReduceSum(dsum, sbuf);
    if (tid == 0) g_denom[row] = dsum + 1.f;
}

// ===========================================================================
extern "C" void kernel_launch(void* const* d_in, const int* in_sizes, int n_in,
                              void* d_out, int out_size) {
    const float* gcn   = (const float*)d_in[0];
    const float* rel   = (const float*)d_in[1];
    const int*   adj   = (const int*)d_in[2];
    const int*   mask  = (const int*)d_in[3];
    const float* W_Q   = (const float*)d_in[4];
    const float* b_Q   = (const float*)d_in[5];
    const float* W_K   = (const float*)d_in[6];
    const float* b_K   = (const float*)d_in[7];
    const float* W_gcn = (const float*)d_in[8];
    const float* b_gcn = (const float*)d_in[9];
    const float* W_out = (const float*)d_in[10];
    const float* b_out = (const float*)d_in[11];
    float* out = (float*)d_out;

    const dim3 thr(256);

    // q = [gcn | rel] @ W_Q + b_Q ; k = gcn @ W_K + b_K   (fp32 FFMA)
    proj_kernel<<<dim3(2, 32), thr>>>(gcn, W_Q,             b_Q, 0, 0);
    proj_kernel<<<dim3(2, 32), thr>>>(rel, W_Q + 256 * 256, nullptr, 0, 1);
    proj_kernel<<<dim3(2, 32), thr>>>(gcn, W_K,             b_K, 1, 0);

    // scores + z-score attention (fp32)
    scores_kernel<<<dim3(8, 8, 16), thr>>>();
    zscore_kernel<<<16 * N_, thr>>>(mask, adj);

    // GCN layers on tensor cores (tf32 mma.sync)
    for (int l = 0; l < L_; l++) {
        axpx_mma<<<dim3(2, 8, 16), thr>>>(gcn, l);
        tw_mma<<<dim3(2, 8, 16), thr>>>(W_gcn, b_gcn, l);
    }

    // residual + output projection on tensor cores
    final_mma<<<dim3(2, 32), thr>>>(gcn, W_out, b_out, out);
}

// round 5
// speedup vs baseline: 2.9691x; 1.2860x over previous
#include <cuda_runtime.h>
#include <cstdint>
#include <math.h>

// Problem constants
constexpr int B_  = 4;
constexpr int N_  = 1024;
constexpr int D_  = 256;
constexpr int H_  = 4;
constexpr int L_  = 2;
constexpr int BN_ = B_ * N_;        // 4096
constexpr int FD_ = D_ * H_ * L_;   // 2048

// Scratch (static device globals)
__device__ float g_qhi[BN_ * D_];
__device__ float g_qlo[BN_ * D_];
__device__ float g_khi[BN_ * D_];
__device__ float g_klo[BN_ * D_];
__device__ float g_attn[16 * N_ * N_];          // 64 MB
__device__ float g_denom[16 * N_];
__device__ float g_tmp[16 * N_ * D_];           // 16 MB
__device__ float g_final[BN_ * FD_];            // 32 MB

// ===========================================================================
// helpers
// ===========================================================================
__device__ __forceinline__ uint32_t smem_u32(const void* p) {
    uint32_t a;
    asm("{ .reg .u64 t; cvta.to.shared.u64 t, %1; cvt.u32.u64 %0, t; }" : "=r"(a) : "l"(p));
    return a;
}
__device__ __forceinline__ uint32_t f2tf(float x) {
    uint32_t r;
    asm("cvt.rna.tf32.f32 %0, %1;" : "=r"(r) : "f"(x));
    return r;
}
__device__ __forceinline__ void mma16n8k8(float d[4], const uint32_t a[4],
                                          const uint32_t b[2]) {
    asm volatile(
        "mma.sync.aligned.m16n8k8.row.col.f32.tf32.tf32.f32 "
        "{%0,%1,%2,%3}, {%4,%5,%6,%7}, {%8,%9}, {%0,%1,%2,%3};"
        : "+f"(d[0]), "+f"(d[1]), "+f"(d[2]), "+f"(d[3])
        : "r"(a[0]), "r"(a[1]), "r"(a[2]), "r"(a[3]), "r"(b[0]), "r"(b[1]));
}

#define CP_A16(dst, src) \
    asm volatile("cp.async.cg.shared.global [%0], [%1], 16;" :: "r"(dst), "l"(src))
#define CP_COMMIT() asm volatile("cp.async.commit_group;")
#define CP_WAIT(n)  asm volatile("cp.async.wait_group %0;" :: "n"(n))

// ===========================================================================
// cp.async 3-stage pipelined tf32 mma core
//   block tile 128x128, K-chunk 32, 256 threads = 8 warps (4m x 2n),
//   warp tile 32x64. fp32 fed raw to tf32 mma (HW truncates mantissa).
// ===========================================================================
constexpr int AS_STR = 36;                 // bank = 4*row + k  (conflict-free)
constexpr int BS_STR = 136;                // bank = 8*k + n    (conflict-free)
constexpr int ASZ = 128 * AS_STR;          // 4608 words
constexpr int BSZ = 32 * BS_STR;           // 4352 words
constexpr int STG = ASZ + BSZ;             // 8960 words / stage
constexpr int MMA_SMEM = 3 * STG * 4;      // 107520 B

__device__ __forceinline__ void mma_issue(const float* __restrict__ A, int lda,
                                          const float* __restrict__ B, int ldb,
                                          int kt, uint32_t sb) {
    const int tid = threadIdx.x;
    const uint32_t da = sb + (uint32_t)((kt % 3) * STG) * 4u;
    const uint32_t db = da + (uint32_t)ASZ * 4u;
    const float* Ak = A + kt * 32;
    const float* Bk = B + (size_t)(kt * 32) * ldb;
#pragma unroll
    for (int e = 0; e < 4; e++) {
        int idx = tid + 256 * e, row = idx >> 3, c4 = idx & 7;
        CP_A16(da + (uint32_t)(row * AS_STR + c4 * 4) * 4u,
               Ak + (size_t)row * lda + c4 * 4);
    }
#pragma unroll
    for (int e = 0; e < 4; e++) {
        int idx = tid + 256 * e, kr = idx >> 5, c4 = idx & 31;
        CP_A16(db + (uint32_t)(kr * BS_STR + c4 * 4) * 4u,
               Bk + (size_t)kr * ldb + c4 * 4);
    }
}

__device__ __forceinline__ void mma_core(const float* __restrict__ A, int lda,
                                         const float* __restrict__ B, int ldb,
                                         int K, float c[2][8][4], uint32_t* sm) {
    const int tid = threadIdx.x;
    const uint32_t sb = smem_u32(sm);
    const int lane = tid & 31, wid = tid >> 5;
    const int wm = (wid >> 1) * 32, wn = (wid & 1) * 64;
    const int qr = lane >> 2, qk = lane & 3;
    const int niter = K >> 5;

    mma_issue(A, lda, B, ldb, 0, sb); CP_COMMIT();
    mma_issue(A, lda, B, ldb, 1, sb); CP_COMMIT();

    for (int kt = 0; kt < niter; kt++) {
        if (kt + 2 < niter) mma_issue(A, lda, B, ldb, kt + 2, sb);
        CP_COMMIT();
        CP_WAIT(1);
        __syncthreads();
        const uint32_t* sA = sm + (kt % 3) * STG;
        const uint32_t* sB = sA + ASZ;
#pragma unroll
        for (int kk = 0; kk < 4; kk++) {
            const int k0 = kk * 8;
            uint32_t af[2][4];
#pragma unroll
            for (int mi = 0; mi < 2; mi++) {
                const int rb = wm + mi * 16 + qr;
                af[mi][0] = sA[(rb)     * AS_STR + k0 + qk];
                af[mi][1] = sA[(rb + 8) * AS_STR + k0 + qk];
                af[mi][2] = sA[(rb)     * AS_STR + k0 + qk + 4];
                af[mi][3] = sA[(rb + 8) * AS_STR + k0 + qk + 4];
            }
#pragma unroll
            for (int ni = 0; ni < 8; ni++) {
                uint32_t bf[2];
                bf[0] = sB[(k0 + qk)     * BS_STR + wn + ni * 8 + qr];
                bf[1] = sB[(k0 + qk + 4) * BS_STR + wn + ni * 8 + qr];
                mma16n8k8(c[0][ni], af[0], bf);
                mma16n8k8(c[1][ni], af[1], bf);
            }
        }
        __syncthreads();
    }
}

// Epilogue: element (mi, half, ni) -> row = wm+mi*16+qr+half*8, col = wn+ni*8+2qk
#define EPILOGUE_LOOP(BODY)                                                   \
    do {                                                                      \
        const int lane = threadIdx.x & 31, wid = threadIdx.x >> 5;            \
        const int wm = (wid >> 1) * 32, wn = (wid & 1) * 64;                  \
        const int qr = lane >> 2, qk = lane & 3;                              \
        _Pragma("unroll")                                                     \
        for (int mi = 0; mi < 2; mi++)                                        \
            _Pragma("unroll")                                                 \
            for (int half = 0; half < 2; half++) {                            \
                const int row = wm + mi * 16 + qr + half * 8;                 \
                _Pragma("unroll")                                             \
                for (int ni = 0; ni < 8; ni++) {                              \
                    const int col = wn + ni * 8 + 2 * qk;                     \
                    float v0 = c[mi][ni][half * 2 + 0];                       \
                    float v1 = c[mi][ni][half * 2 + 1];                       \
                    BODY                                                      \
                }                                                             \
            }                                                                 \
    } while (0)

// ===========================================================================
// Kernel: T[bh] = a[bh] @ X[b] + X[b]   (K = 1024) -> g_tmp
// grid (2 ntiles, 8 mtiles, 16 bh)
// ===========================================================================
__global__ __launch_bounds__(256) void axpx_mma(const float* __restrict__ gcn, int l) {
    extern __shared__ uint32_t sm[];
    const int bh = blockIdx.z, b = bh >> 2, h = bh & 3;
    const int m0 = blockIdx.y * 128, n0 = blockIdx.x * 128;
    const float* A = g_attn + (size_t)bh * N_ * N_ + (size_t)m0 * N_;
    const float* X; int ldx;
    if (l == 0) { X = gcn + (size_t)b * N_ * D_; ldx = D_; }
    else        { X = g_final + (size_t)b * N_ * FD_ + 2 * h * D_; ldx = FD_; }

    float c[2][8][4] = {};
    mma_core(A, N_, X + n0, ldx, N_, c, sm);

    const float* Xe = X + (size_t)m0 * ldx + n0;
    float* C = g_tmp + (size_t)bh * N_ * D_ + (size_t)m0 * D_ + n0;
    EPILOGUE_LOOP({
        v0 += Xe[(size_t)row * ldx + col];
        v1 += Xe[(size_t)row * ldx + col + 1];
        *(float2*)(C + (size_t)row * D_ + col) = make_float2(v0, v1);
    });
}

// ===========================================================================
// Kernel: g_final[:, idx*D:] = relu((T @ W_gcn[idx] + 2*b_gcn[idx]) / denom)
// grid (2, 8, 16), K = 256
// ===========================================================================
__global__ __launch_bounds__(256) void tw_mma(const float* __restrict__ Wg,
                                              const float* __restrict__ bg, int l) {
    extern __shared__ uint32_t sm[];
    const int bh = blockIdx.z, b = bh >> 2, h = bh & 3;
    const int idx = h * L_ + l;
    const int m0 = blockIdx.y * 128, n0 = blockIdx.x * 128;
    const float* A = g_tmp + (size_t)bh * N_ * D_ + (size_t)m0 * D_;
    const float* Bw = Wg + (size_t)idx * D_ * D_ + n0;

    float c[2][8][4] = {};
    mma_core(A, D_, Bw, D_, D_, c, sm);

    float* C = g_final + (size_t)b * N_ * FD_ + (size_t)idx * D_ + (size_t)m0 * FD_ + n0;
    const float* dn = g_denom + (size_t)bh * N_ + m0;
    const float* bgp = bg + (size_t)idx * D_ + n0;
    EPILOGUE_LOOP({
        const float inv = 1.f / dn[row];
        v0 = fmaxf((v0 + 2.f * bgp[col])     * inv, 0.f);
        v1 = fmaxf((v1 + 2.f * bgp[col + 1]) * inv, 0.f);
        *(float2*)(C + (size_t)row * FD_ + col) = make_float2(v0, v1);
    });
}

// ===========================================================================
// Kernel: out = gcn + g_final @ W_out + b_out   (K = 2048), grid (2, 32)
// ===========================================================================
__global__ __launch_bounds__(256) void final_mma(const float* __restrict__ gcn,
                                                 const float* __restrict__ Wo,
                                                 const float* __restrict__ bo,
                                                 float* __restrict__ out) {
    extern __shared__ uint32_t sm[];
    const int m0 = blockIdx.y * 128, n0 = blockIdx.x * 128;
    const float* A = g_final + (size_t)m0 * FD_;

    float c[2][8][4] = {};
    mma_core(A, FD_, Wo + n0, D_, FD_, c, sm);

    const float* G = gcn + (size_t)m0 * D_ + n0;
    float* C = out + (size_t)m0 * D_ + n0;
    const float* bop = bo + n0;
    EPILOGUE_LOOP({
        v0 += G[(size_t)row * D_ + col]     + bop[col];
        v1 += G[(size_t)row * D_ + col + 1] + bop[col + 1];
        *(float2*)(C + (size_t)row * D_ + col) = make_float2(v0, v1);
    });
}

// ===========================================================================
// Scores via 3xTF32 (hi/lo split, fp32-accurate): per (bh) NT GEMM, K=64
//   scores = Qhi*Khi^T + Qhi*Klo^T + Qlo*Khi^T
// grid (8 ntiles, 8 mtiles, 16 bh), 256 threads, single-shot SMEM (no K loop)
// ===========================================================================
constexpr int SC_STR = 68;                 // bank = 4*row + k (conflict-free)
constexpr int SC_TILE = 128 * SC_STR;      // 8704 words per tile
constexpr int SC_SMEM = 4 * SC_TILE * 4;   // 139264 B

__global__ __launch_bounds__(256) void scores3_mma() {
    extern __shared__ uint32_t sm[];
    const int bh = blockIdx.z, b = bh >> 2, h = bh & 3;
    const int m0 = blockIdx.y * 128, n0 = blockIdx.x * 128;
    const int tid = threadIdx.x;
    const uint32_t sb = smem_u32(sm);

    const size_t qoff = ((size_t)(b * N_ + m0)) * D_ + h * 64;
    const size_t koff = ((size_t)(b * N_ + n0)) * D_ + h * 64;
    const float* srcs[4] = {g_qhi + qoff, g_qlo + qoff, g_khi + koff, g_klo + koff};
#pragma unroll
    for (int t = 0; t < 4; t++) {
        const uint32_t dst = sb + (uint32_t)(t * SC_TILE) * 4u;
        const float* s = srcs[t];
#pragma unroll
        for (int e = 0; e < 8; e++) {
            int idx = tid + 256 * e, row = idx >> 4, c4 = idx & 15;
            CP_A16(dst + (uint32_t)(row * SC_STR + c4 * 4) * 4u,
                   s + (size_t)row * D_ + c4 * 4);
        }
    }
    CP_COMMIT();
    CP_WAIT(0);
    __syncthreads();

    const uint32_t* sQh = sm;
    const uint32_t* sQl = sm + SC_TILE;
    const uint32_t* sKh = sm + 2 * SC_TILE;
    const uint32_t* sKl = sm + 3 * SC_TILE;

    const int lane = tid & 31, wid = tid >> 5;
    const int wm = (wid >> 1) * 32, wn = (wid & 1) * 64;
    const int qr = lane >> 2, qk = lane & 3;

    float c[2][8][4] = {};
#pragma unroll
    for (int kk = 0; kk < 8; kk++) {
        const int k0 = kk * 8;
        uint32_t ah[2][4], al[2][4];
#pragma unroll
        for (int mi = 0; mi < 2; mi++) {
            const int rb = wm + mi * 16 + qr;
            ah[mi][0] = sQh[(rb)     * SC_STR + k0 + qk];
            ah[mi][1] = sQh[(rb + 8) * SC_STR + k0 + qk];
            ah[mi][2] = sQh[(rb)     * SC_STR + k0 + qk + 4];
            ah[mi][3] = sQh[(rb + 8) * SC_STR + k0 + qk + 4];
            al[mi][0] = sQl[(rb)     * SC_STR + k0 + qk];
            al[mi][1] = sQl[(rb + 8) * SC_STR + k0 + qk];
            al[mi][2] = sQl[(rb)     * SC_STR + k0 + qk + 4];
            al[mi][3] = sQl[(rb + 8) * SC_STR + k0 + qk + 4];
        }
#pragma unroll
        for (int ni = 0; ni < 8; ni++) {
            const int nr = wn + ni * 8 + qr;
            uint32_t bh2[2], bl2[2];
            bh2[0] = sKh[nr * SC_STR + k0 + qk];
            bh2[1] = sKh[nr * SC_STR + k0 + qk + 4];
            bl2[0] = sKl[nr * SC_STR + k0 + qk];
            bl2[1] = sKl[nr * SC_STR + k0 + qk + 4];
#pragma unroll
            for (int mi = 0; mi < 2; mi++) {
                mma16n8k8(c[mi][ni], ah[mi], bh2);
                mma16n8k8(c[mi][ni], ah[mi], bl2);
                mma16n8k8(c[mi][ni], al[mi], bh2);
            }
        }
    }

    float* C = g_attn + (size_t)bh * N_ * N_ + (size_t)m0 * N_ + n0;
    EPILOGUE_LOOP({
        *(float2*)(C + (size_t)row * N_ + col) = make_float2(v0, v1);
    });
}

// ===========================================================================
// Merged projection (FFMA, fp32-exact), writes tf32 hi/lo pairs.
// grid (2 ntiles, 32 mtiles, 2): z=0: q = [gcn|rel] @ W_Q + b_Q (K=512)
//                                z=1: k = gcn @ W_K + b_K       (K=256)
// ===========================================================================
__global__ __launch_bounds__(256) void proj_kernel(const float* __restrict__ gcn,
                                                   const float* __restrict__ rel,
                                                   const float* __restrict__ W_Q,
                                                   const float* __restrict__ b_Q,
                                                   const float* __restrict__ W_K,
                                                   const float* __restrict__ b_K) {
    __shared__ float As[8][128];
    __shared__ float Bs[8][128];
    const int z = blockIdx.z;
    const int K = z ? 256 : 512;
    const float* W = z ? W_K : W_Q;
    const float* bias = z ? b_K : b_Q;

    const int tid = threadIdx.x;
    const int tx = tid & 15, ty = tid >> 4;
    const int arow = tid >> 1, akb = (tid & 1) * 4;
    const int bkr = tid >> 5, bnb = (tid & 31) * 4;
    const int r = blockIdx.y * 128 + arow;
    const int nbase = blockIdx.x * 128;

    float acc[8][8] = {};
    for (int k0 = 0; k0 < K; k0 += 8) {
        const int kk0 = k0 + akb;
        const float* srcA = (kk0 < 256) ? (gcn + (size_t)r * D_ + kk0)
                                        : (rel + (size_t)r * D_ + kk0 - 256);
        float4 av = *reinterpret_cast<const float4*>(srcA);
        As[akb + 0][arow] = av.x; As[akb + 1][arow] = av.y;
        As[akb + 2][arow] = av.z; As[akb + 3][arow] = av.w;
        float4 bv = *reinterpret_cast<const float4*>(W + (size_t)(k0 + bkr) * D_ + nbase + bnb);
        *reinterpret_cast<float4*>(&Bs[bkr][bnb]) = bv;
        __syncthreads();
#pragma unroll
        for (int kk = 0; kk < 8; kk++) {
            float ra[8], rb[8];
#pragma unroll
            for (int i = 0; i < 8; i++) ra[i] = As[kk][ty * 8 + i];
#pragma unroll
            for (int j = 0; j < 8; j++) rb[j] = Bs[kk][tx * 8 + j];
#pragma unroll
            for (int i = 0; i < 8; i++)
#pragma unroll
                for (int j = 0; j < 8; j++)
                    acc[i][j] = fmaf(ra[i], rb[j], acc[i][j]);
        }
        __syncthreads();
    }

    float* Chi = z ? g_khi : g_qhi;
    float* Clo = z ? g_klo : g_qlo;
    const int m0 = blockIdx.y * 128 + ty * 8;
    const int n0 = nbase + tx * 8;
#pragma unroll
    for (int i = 0; i < 8; i++)
#pragma unroll
        for (int j = 0; j < 8; j++) {
            float v = acc[i][j] + bias[n0 + j];
            uint32_t hb = f2tf(v);
            float hf = __uint_as_float(hb);
            uint32_t lb = f2tf(v - hf);
            Chi[(size_t)(m0 + i) * D_ + n0 + j] = hf;
            Clo[(size_t)(m0 + i) * D_ + n0 + j] = __uint_as_float(lb);
        }
}

// ---------------------------------------------------------------------------
// z-score attention (unchanged)
// ---------------------------------------------------------------------------
__device__ __forceinline__ float blockReduceSum(float v, float* sbuf) {
    const int tid = threadIdx.x;
#pragma unroll
    for (int o = 16; o > 0; o >>= 1) v += __shfl_xor_sync(0xffffffffu, v, o);
    if ((tid & 31) == 0) sbuf[tid >> 5] = v;
    __syncthreads();
    if (tid < 8) {
        v = sbuf[tid];
#pragma unroll
        for (int o = 4; o > 0; o >>= 1) v += __shfl_xor_sync(0xffu, v, o);
        if (tid == 0) sbuf[0] = v;
    }
    __syncthreads();
    float r = sbuf[0];
    __syncthreads();
    return r;
}
__device__ __forceinline__ float blockReduceMax(float v, float* sbuf) {
    const int tid = threadIdx.x;
#pragma unroll
    for (int o = 16; o > 0; o >>= 1) v = fmaxf(v, __shfl_xor_sync(0xffffffffu, v, o));
    if ((tid & 31) == 0) sbuf[tid >> 5] = v;
    __syncthreads();
    if (tid < 8) {
        v = sbuf[tid];
#pragma unroll
        for (int o = 4; o > 0; o >>= 1) v = fmaxf(v, __shfl_xor_sync(0xffu, v, o));
        if (tid == 0) sbuf[0] = v;
    }
    __syncthreads();
    float r = sbuf[0];
    __syncthreads();
    return r;
}

__global__ __launch_bounds__(256) void zscore_kernel(const int* __restrict__ mask,
                                                     const int* __restrict__ adj) {
    const int row = blockIdx.x;
    const int i  = row & (N_ - 1);
    const int bh = row >> 10;
    const int b  = bh >> 2;
    float* sc = g_attn + (size_t)row * N_;
    const int* adjrow = adj + ((size_t)b * N_ + i) * N_;
    const int* mrow = mask + (size_t)b * N_;
    const int tid = threadIdx.x;
    __shared__ float sbuf[8];

    float v[4], av[4];
    int mv[4];
    float cnt = 0.f, s = 0.f;
#pragma unroll
    for (int e = 0; e < 4; e++) {
        int j = tid + e * 256;
        v[e] = sc[j];
        mv[e] = (mrow[j] == 0);
        av[e] = (float)adjrow[j];
        if (mv[e]) { cnt += 1.f; s += v[e]; }
    }
    cnt = blockReduceSum(cnt, sbuf);
    s   = blockReduceSum(s, sbuf);
    const float mean = s / (cnt + 1e-4f);

    float ss = 0.f;
#pragma unroll
    for (int e = 0; e < 4; e++) {
        float d = v[e] - mean;
        if (mv[e]) ss += d * d;
    }
    ss = blockReduceSum(ss, sbuf);
    const float stdv = sqrtf(ss / (cnt + 1e-4f) + 1e-10f);

    float s2[4];
    int keep[4];
#pragma unroll
    for (int e = 0; e < 4; e++) {
        float z = (v[e] - mean) / (stdv + 1e-4f);
        if (!mv[e]) z = 0.f;
        int th = (z < 0.f);
        s2[e] = (th || !mv[e]) ? -1e9f : z;
        keep[e] = (mv[e] && !th && (av[e] != 0.f));
    }
    float mx = -1e30f;
#pragma unroll
    for (int e = 0; e < 4; e++) mx = fmaxf(mx, s2[e]);
    mx = blockReduceMax(mx, sbuf);

    float ev[4], se = 0.f;
#pragma unroll
    for (int e = 0; e < 4; e++) {
        float ee = mv[e] ? (expf(s2[e] - mx) * av[e]) : 0.f;
        ee += 1e-10f;
        ev[e] = ee;
        se += ee;
    }
    se = blockReduceSum(se, sbuf);

    float dsum = 0.f;
#pragma unroll
    for (int e = 0; e < 4; e++) {
        int j = tid + e * 256;
        float w = keep[e] ? (ev[e] / se) : 0.f;
        sc[j] = w;
        dsum += w;
    }
    dsum = blockReduceSum(dsum, sbuf);
    if (tid == 0) g_denom[row] = dsum + 1.f;
}

// ===========================================================================
extern "C" void kernel_launch(void* const* d_in, const int* in_sizes, int n_in,
                              void* d_out, int out_size) {
    const float* gcn   = (const float*)d_in[0];
    const float* rel   = (const float*)d_in[1];
    const int*   adj   = (const int*)d_in[2];
    const int*   mask  = (const int*)d_in[3];
    const float* W_Q   = (const float*)d_in[4];
    const float* b_Q   = (const float*)d_in[5];
    const float* W_K   = (const float*)d_in[6];
    const float* b_K   = (const float*)d_in[7];
    const float* W_gcn = (const float*)d_in[8];
    const float* b_gcn = (const float*)d_in[9];
    const float* W_out = (const float*)d_in[10];
    const float* b_out = (const float*)d_in[11];
    float* out = (float*)d_out;

    cudaFuncSetAttribute(axpx_mma,    cudaFuncAttributeMaxDynamicSharedMemorySize, MMA_SMEM);
    cudaFuncSetAttribute(tw_mma,      cudaFuncAttributeMaxDynamicSharedMemorySize, MMA_SMEM);
    cudaFuncSetAttribute(final_mma,   cudaFuncAttributeMaxDynamicSharedMemorySize, MMA_SMEM);
    cudaFuncSetAttribute(scores3_mma, cudaFuncAttributeMaxDynamicSharedMemorySize, SC_SMEM);

    const dim3 thr(256);

    // q/k projections (fp32 FFMA, single merged launch) -> tf32 hi/lo
    proj_kernel<<<dim3(2, 32, 2), thr>>>(gcn, rel, W_Q, b_Q, W_K, b_K);

    // scores (3xTF32, fp32-accurate) + z-score attention
    scores3_mma<<<dim3(8, 8, 16), thr, SC_SMEM>>>();
    zscore_kernel<<<16 * N_, thr>>>(mask, adj);

    // GCN layers (tf32 mma.sync, cp.async pipelined)
    for (int l = 0; l < L_; l++) {
        axpx_mma<<<dim3(2, 8, 16), thr, MMA_SMEM>>>(gcn, l);
        tw_mma<<<dim3(2, 8, 16), thr, MMA_SMEM>>>(W_gcn, b_gcn, l);
    }

    // residual + output projection
    final_mma<<<dim3(2, 32), thr, MMA_SMEM>>>(gcn, W_out, b_out, out);
}

// round 6
// speedup vs baseline: 3.0340x; 1.0219x over previous
#include <cuda_runtime.h>
#include <cstdint>
#include <math.h>

// Problem constants
constexpr int B_  = 4;
constexpr int N_  = 1024;
constexpr int D_  = 256;
constexpr int H_  = 4;
constexpr int L_  = 2;
constexpr int BN_ = B_ * N_;        // 4096
constexpr int FD_ = D_ * H_ * L_;   // 2048

// Scratch (static device globals)
__device__ float g_qhi[BN_ * D_];
__device__ float g_qlo[BN_ * D_];
__device__ float g_khi[BN_ * D_];
__device__ float g_klo[BN_ * D_];
__device__ float g_attn[16 * N_ * N_];          // 64 MB
__device__ float g_denom[16 * N_];
__device__ float g_tmp[16 * N_ * D_];           // 16 MB
__device__ float g_final[BN_ * FD_];            // 32 MB
__device__ float g_part[4 * BN_ * D_];          // 16 MB (split-K partials)
__device__ float g_gcnr[BN_ * D_];              // 4 MB  (rna-rounded gcn)
__device__ float g_wgr[8 * D_ * D_];            // 2 MB  (rna-rounded W_gcn)
__device__ float g_wor[FD_ * D_];               // 2 MB  (rna-rounded W_out)
__device__ uint32_t g_adjbits[B_ * N_ * (N_ / 32)];  // 512 KB

// ===========================================================================
// helpers
// ===========================================================================
__device__ __forceinline__ uint32_t smem_u32(const void* p) {
    uint32_t a;
    asm("{ .reg .u64 t; cvta.to.shared.u64 t, %1; cvt.u32.u64 %0, t; }" : "=r"(a) : "l"(p));
    return a;
}
__device__ __forceinline__ uint32_t f2tf(float x) {
    uint32_t r;
    asm("cvt.rna.tf32.f32 %0, %1;" : "=r"(r) : "f"(x));
    return r;
}
__device__ __forceinline__ float rna(float x) { return __uint_as_float(f2tf(x)); }

__device__ __forceinline__ void mma16n8k8(float d[4], const uint32_t a[4],
                                          const uint32_t b[2]) {
    asm volatile(
        "mma.sync.aligned.m16n8k8.row.col.f32.tf32.tf32.f32 "
        "{%0,%1,%2,%3}, {%4,%5,%6,%7}, {%8,%9}, {%0,%1,%2,%3};"
        : "+f"(d[0]), "+f"(d[1]), "+f"(d[2]), "+f"(d[3])
        : "r"(a[0]), "r"(a[1]), "r"(a[2]), "r"(a[3]), "r"(b[0]), "r"(b[1]));
}

#define CP_A16(dst, src) \
    asm volatile("cp.async.cg.shared.global [%0], [%1], 16;" :: "r"(dst), "l"(src))
#define CP_COMMIT() asm volatile("cp.async.commit_group;")
#define CP_WAIT(n)  asm volatile("cp.async.wait_group %0;" :: "n"(n))

// ===========================================================================
// 512-thread pipelined tf32 mma core: block tile 128(M) x 256(N), K-chunk 32,
// 16 warps (4m x 4n), warp tile 32x64, 3-stage cp.async.
// ===========================================================================
constexpr int AS_STR = 36;                 // bank = 4*row + k   (conflict-free)
constexpr int BS_STR = 264;                // bank = 8*k + n     (conflict-free)
constexpr int ASZ = 128 * AS_STR;          // 4608 words
constexpr int BSZ = 32 * BS_STR;           // 8448 words
constexpr int STG = ASZ + BSZ;             // 13056 words / stage
constexpr int MMA_SMEM = 3 * STG * 4;      // 156672 B

__device__ __forceinline__ void mma_issue(const float* __restrict__ A, int lda,
                                          const float* __restrict__ B, int ldb,
                                          int kt, uint32_t sb) {
    const int tid = threadIdx.x;
    const uint32_t da = sb + (uint32_t)((kt % 3) * STG) * 4u;
    const uint32_t db = da + (uint32_t)ASZ * 4u;
    const float* Ak = A + kt * 32;
    const float* Bk = B + (size_t)(kt * 32) * ldb;
#pragma unroll
    for (int e = 0; e < 2; e++) {
        int idx = tid + 512 * e, row = idx >> 3, c4 = idx & 7;
        CP_A16(da + (uint32_t)(row * AS_STR + c4 * 4) * 4u,
               Ak + (size_t)row * lda + c4 * 4);
    }
#pragma unroll
    for (int e = 0; e < 4; e++) {
        int idx = tid + 512 * e, kr = idx >> 6, c4 = idx & 63;
        CP_A16(db + (uint32_t)(kr * BS_STR + c4 * 4) * 4u,
               Bk + (size_t)kr * ldb + c4 * 4);
    }
}

__device__ __forceinline__ void mma_core(const float* __restrict__ A, int lda,
                                         const float* __restrict__ B, int ldb,
                                         int K, float c[2][8][4], uint32_t* sm) {
    const int tid = threadIdx.x;
    const uint32_t sb = smem_u32(sm);
    const int lane = tid & 31, wid = tid >> 5;
    const int wm = (wid >> 2) * 32, wn = (wid & 3) * 64;
    const int qr = lane >> 2, qk = lane & 3;
    const int niter = K >> 5;

    mma_issue(A, lda, B, ldb, 0, sb); CP_COMMIT();
    mma_issue(A, lda, B, ldb, 1, sb); CP_COMMIT();

    for (int kt = 0; kt < niter; kt++) {
        if (kt + 2 < niter) mma_issue(A, lda, B, ldb, kt + 2, sb);
        CP_COMMIT();
        CP_WAIT(1);
        __syncthreads();
        const uint32_t* sA = sm + (kt % 3) * STG;
        const uint32_t* sB = sA + ASZ;
#pragma unroll
        for (int kk = 0; kk < 4; kk++) {
            const int k0 = kk * 8;
            uint32_t af[2][4];
#pragma unroll
            for (int mi = 0; mi < 2; mi++) {
                const int rb = wm + mi * 16 + qr;
                af[mi][0] = sA[(rb)     * AS_STR + k0 + qk];
                af[mi][1] = sA[(rb + 8) * AS_STR + k0 + qk];
                af[mi][2] = sA[(rb)     * AS_STR + k0 + qk + 4];
                af[mi][3] = sA[(rb + 8) * AS_STR + k0 + qk + 4];
            }
#pragma unroll
            for (int ni = 0; ni < 8; ni++) {
                uint32_t bf[2];
                bf[0] = sB[(k0 + qk)     * BS_STR + wn + ni * 8 + qr];
                bf[1] = sB[(k0 + qk + 4) * BS_STR + wn + ni * 8 + qr];
                mma16n8k8(c[0][ni], af[0], bf);
                mma16n8k8(c[1][ni], af[1], bf);
            }
        }
        __syncthreads();
    }
}

// Epilogue: row = wm+mi*16+qr+half*8, col = wn+ni*8+2qk  (cols span 256)
#define EPILOGUE_LOOP(BODY)                                                   \
    do {                                                                      \
        const int lane = threadIdx.x & 31, wid = threadIdx.x >> 5;            \
        const int wm = (wid >> 2) * 32, wn = (wid & 3) * 64;                  \
        const int qr = lane >> 2, qk = lane & 3;                              \
        _Pragma("unroll")                                                     \
        for (int mi = 0; mi < 2; mi++)                                        \
            _Pragma("unroll")                                                 \
            for (int half = 0; half < 2; half++) {                            \
                const int row = wm + mi * 16 + qr + half * 8;                 \
                _Pragma("unroll")                                             \
                for (int ni = 0; ni < 8; ni++) {                              \
                    const int col = wn + ni * 8 + 2 * qk;                     \
                    float v0 = c[mi][ni][half * 2 + 0];                       \
                    float v1 = c[mi][ni][half * 2 + 1];                       \
                    BODY                                                      \
                }                                                             \
            }                                                                 \
    } while (0)

// ===========================================================================
// T[bh] = a[bh] @ X[b] + X[b]  (K=1024) -> g_tmp (rna-rounded)
// grid (8 mtiles, 16 bh), 512 thr
// ===========================================================================
__global__ __launch_bounds__(512) void axpx_mma(const float* __restrict__ gcn, int l) {
    extern __shared__ uint32_t sm[];
    const int bh = blockIdx.y, b = bh >> 2, h = bh & 3;
    const int m0 = blockIdx.x * 128;
    const float* A = g_attn + (size_t)bh * N_ * N_ + (size_t)m0 * N_;
    const float* Xg;        // GEMM operand (rounded)
    const float* Xe;        // epilogue addend
    int ldx;
    if (l == 0) { Xg = g_gcnr + (size_t)b * N_ * D_; Xe = gcn + (size_t)b * N_ * D_; ldx = D_; }
    else {
        Xg = g_final + (size_t)b * N_ * FD_ + 2 * h * D_;
        Xe = Xg; ldx = FD_;
    }

    float c[2][8][4] = {};
    mma_core(A, N_, Xg, ldx, N_, c, sm);

    const float* Xa = Xe + (size_t)m0 * ldx;
    float* C = g_tmp + (size_t)bh * N_ * D_ + (size_t)m0 * D_;
    EPILOGUE_LOOP({
        v0 = rna(v0 + Xa[(size_t)row * ldx + col]);
        v1 = rna(v1 + Xa[(size_t)row * ldx + col + 1]);
        *(float2*)(C + (size_t)row * D_ + col) = make_float2(v0, v1);
    });
}

// ===========================================================================
// g_final[:, idx*D:] = relu((T @ W_gcn[idx] + 2*b_gcn[idx]) / denom)  (rounded)
// grid (8 mtiles, 16 bh), K=256
// ===========================================================================
__global__ __launch_bounds__(512) void tw_mma(const float* __restrict__ bg, int l) {
    extern __shared__ uint32_t sm[];
    const int bh = blockIdx.y, b = bh >> 2, h = bh & 3;
    const int idx = h * L_ + l;
    const int m0 = blockIdx.x * 128;
    const float* A = g_tmp + (size_t)bh * N_ * D_ + (size_t)m0 * D_;
    const float* Bw = g_wgr + (size_t)idx * D_ * D_;

    float c[2][8][4] = {};
    mma_core(A, D_, Bw, D_, D_, c, sm);

    float* C = g_final + (size_t)b * N_ * FD_ + (size_t)idx * D_ + (size_t)m0 * FD_;
    const float* dn = g_denom + (size_t)bh * N_ + m0;
    const float* bgp = bg + (size_t)idx * D_;
    EPILOGUE_LOOP({
        const float inv = 1.f / dn[row];
        v0 = rna(fmaxf((v0 + 2.f * bgp[col])     * inv, 0.f));
        v1 = rna(fmaxf((v1 + 2.f * bgp[col + 1]) * inv, 0.f));
        *(float2*)(C + (size_t)row * FD_ + col) = make_float2(v0, v1);
    });
}

// ===========================================================================
// Split-K output GEMM: partial[kc] = g_final[:, kc*512:+512] @ W_out[rows kc*512:]
// grid (4 kchunks, 32 mtiles)
// ===========================================================================
__global__ __launch_bounds__(512) void final_mma() {
    extern __shared__ uint32_t sm[];
    const int kc = blockIdx.x, m0 = blockIdx.y * 128;
    const float* A = g_final + (size_t)m0 * FD_ + kc * 512;
    const float* Bw = g_wor + (size_t)kc * 512 * D_;

    float c[2][8][4] = {};
    mma_core(A, FD_, Bw, D_, 512, c, sm);

    float* C = g_part + (size_t)kc * BN_ * D_ + (size_t)m0 * D_;
    EPILOGUE_LOOP({
        *(float2*)(C + (size_t)row * D_ + col) = make_float2(v0, v1);
    });
}

// out = gcn + sum_k part[k] + b_out ; grid 1024 x 256, float4 per thread
__global__ __launch_bounds__(256) void reduce_final(const float* __restrict__ gcn,
                                                    const float* __restrict__ bo,
                                                    float* __restrict__ out) {
    const int i = blockIdx.x * 256 + threadIdx.x;     // float4 index, 262144 total
    const float4 p0 = ((const float4*)g_part)[i];
    const float4 p1 = ((const float4*)(g_part + (size_t)BN_ * D_))[i];
    const float4 p2 = ((const float4*)(g_part + (size_t)2 * BN_ * D_))[i];
    const float4 p3 = ((const float4*)(g_part + (size_t)3 * BN_ * D_))[i];
    const float4 g  = ((const float4*)gcn)[i];
    const float4 bb = ((const float4*)bo)[i & 63];
    float4 r;
    r.x = g.x + ((p0.x + p1.x) + (p2.x + p3.x)) + bb.x;
    r.y = g.y + ((p0.y + p1.y) + (p2.y + p3.y)) + bb.y;
    r.z = g.z + ((p0.z + p1.z) + (p2.z + p3.z)) + bb.z;
    r.w = g.w + ((p0.w + p1.w) + (p2.w + p3.w)) + bb.w;
    ((float4*)out)[i] = r;
}

// ===========================================================================
// Prep: rna-rounded copies + adj bit-pack
// ===========================================================================
__global__ void round_copy(const float* __restrict__ src, float* __restrict__ dst) {
    const int i = blockIdx.x * 256 + threadIdx.x;
    float4 v = ((const float4*)src)[i];
    v.x = rna(v.x); v.y = rna(v.y); v.z = rna(v.z); v.w = rna(v.w);
    ((float4*)dst)[i] = v;
}

__global__ void pack_adj(const int* __restrict__ adj) {
    const int i = blockIdx.x * 256 + threadIdx.x;   // element index
    const uint32_t bit = (adj[i] != 0);
    const uint32_t w = __ballot_sync(0xffffffffu, bit);
    if ((threadIdx.x & 31) == 0) g_adjbits[i >> 5] = w;
}

// ===========================================================================
// Scores via 3xTF32 (hi/lo split): grid (8 ntiles, 8 mtiles, 16 bh), 256 thr
// ===========================================================================
constexpr int SC_STR = 68;
constexpr int SC_TILE = 128 * SC_STR;
constexpr int SC_SMEM = 4 * SC_TILE * 4;

#define EPILOGUE_LOOP8(BODY)                                                  \
    do {                                                                      \
        const int lane = threadIdx.x & 31, wid = threadIdx.x >> 5;            \
        const int wm = (wid >> 1) * 32, wn = (wid & 1) * 64;                  \
        const int qr = lane >> 2, qk = lane & 3;                              \
        _Pragma("unroll")                                                     \
        for (int mi = 0; mi < 2; mi++)                                        \
            _Pragma("unroll")                                                 \
            for (int half = 0; half < 2; half++) {                            \
                const int row = wm + mi * 16 + qr + half * 8;                 \
                _Pragma("unroll")                                             \
                for (int ni = 0; ni < 8; ni++) {                              \
                    const int col = wn + ni * 8 + 2 * qk;                     \
                    float v0 = c[mi][ni][half * 2 + 0];                       \
                    float v1 = c[mi][ni][half * 2 + 1];                       \
                    BODY                                                      \
                }                                                             \
            }                                                                 \
    } while (0)

__global__ __launch_bounds__(256) void scores3_mma() {
    extern __shared__ uint32_t sm[];
    const int bh = blockIdx.z, b = bh >> 2, h = bh & 3;
    const int m0 = blockIdx.y * 128, n0 = blockIdx.x * 128;
    const int tid = threadIdx.x;
    const uint32_t sb = smem_u32(sm);

    const size_t qoff = ((size_t)(b * N_ + m0)) * D_ + h * 64;
    const size_t koff = ((size_t)(b * N_ + n0)) * D_ + h * 64;
    const float* srcs[4] = {g_qhi + qoff, g_qlo + qoff, g_khi + koff, g_klo + koff};
#pragma unroll
    for (int t = 0; t < 4; t++) {
        const uint32_t dst = sb + (uint32_t)(t * SC_TILE) * 4u;
        const float* s = srcs[t];
#pragma unroll
        for (int e = 0; e < 8; e++) {
            int idx = tid + 256 * e, row = idx >> 4, c4 = idx & 15;
            CP_A16(dst + (uint32_t)(row * SC_STR + c4 * 4) * 4u,
                   s + (size_t)row * D_ + c4 * 4);
        }
    }
    CP_COMMIT();
    CP_WAIT(0);
    __syncthreads();

    const uint32_t* sQh = sm;
    const uint32_t* sQl = sm + SC_TILE;
    const uint32_t* sKh = sm + 2 * SC_TILE;
    const uint32_t* sKl = sm + 3 * SC_TILE;

    const int lane = tid & 31, wid = tid >> 5;
    const int wm = (wid >> 1) * 32, wn = (wid & 1) * 64;
    const int qr = lane >> 2, qk = lane & 3;

    float c[2][8][4] = {};
#pragma unroll
    for (int kk = 0; kk < 8; kk++) {
        const int k0 = kk * 8;
        uint32_t ah[2][4], al[2][4];
#pragma unroll
        for (int mi = 0; mi < 2; mi++) {
            const int rb = wm + mi * 16 + qr;
            ah[mi][0] = sQh[(rb)     * SC_STR + k0 + qk];
            ah[mi][1] = sQh[(rb + 8) * SC_STR + k0 + qk];
            ah[mi][2] = sQh[(rb)     * SC_STR + k0 + qk + 4];
            ah[mi][3] = sQh[(rb + 8) * SC_STR + k0 + qk + 4];
            al[mi][0] = sQl[(rb)     * SC_STR + k0 + qk];
            al[mi][1] = sQl[(rb + 8) * SC_STR + k0 + qk];
            al[mi][2] = sQl[(rb)     * SC_STR + k0 + qk + 4];
            al[mi][3] = sQl[(rb + 8) * SC_STR + k0 + qk + 4];
        }
#pragma unroll
        for (int ni = 0; ni < 8; ni++) {
            const int nr = wn + ni * 8 + qr;
            uint32_t bh2[2], bl2[2];
            bh2[0] = sKh[nr * SC_STR + k0 + qk];
            bh2[1] = sKh[nr * SC_STR + k0 + qk + 4];
            bl2[0] = sKl[nr * SC_STR + k0 + qk];
            bl2[1] = sKl[nr * SC_STR + k0 + qk + 4];
#pragma unroll
            for (int mi = 0; mi < 2; mi++) {
                mma16n8k8(c[mi][ni], ah[mi], bh2);
                mma16n8k8(c[mi][ni], ah[mi], bl2);
                mma16n8k8(c[mi][ni], al[mi], bh2);
            }
        }
    }

    float* C = g_attn + (size_t)bh * N_ * N_ + (size_t)m0 * N_ + n0;
    EPILOGUE_LOOP8({
        *(float2*)(C + (size_t)row * N_ + col) = make_float2(v0, v1);
    });
}

// ===========================================================================
// Merged projection (FFMA fp32) -> tf32 hi/lo pairs
// grid (2 ntiles, 32 mtiles, 2)
// ===========================================================================
__global__ __launch_bounds__(256) void proj_kernel(const float* __restrict__ gcn,
                                                   const float* __restrict__ rel,
                                                   const float* __restrict__ W_Q,
                                                   const float* __restrict__ b_Q,
                                                   const float* __restrict__ W_K,
                                                   const float* __restrict__ b_K) {
    __shared__ float As[8][128];
    __shared__ float Bs[8][128];
    const int z = blockIdx.z;
    const int K = z ? 256 : 512;
    const float* W = z ? W_K : W_Q;
    const float* bias = z ? b_K : b_Q;

    const int tid = threadIdx.x;
    const int tx = tid & 15, ty = tid >> 4;
    const int arow = tid >> 1, akb = (tid & 1) * 4;
    const int bkr = tid >> 5, bnb = (tid & 31) * 4;
    const int r = blockIdx.y * 128 + arow;
    const int nbase = blockIdx.x * 128;

    float acc[8][8] = {};
    for (int k0 = 0; k0 < K; k0 += 8) {
        const int kk0 = k0 + akb;
        const float* srcA = (kk0 < 256) ? (gcn + (size_t)r * D_ + kk0)
                                        : (rel + (size_t)r * D_ + kk0 - 256);
        float4 av = *reinterpret_cast<const float4*>(srcA);
        As[akb + 0][arow] = av.x; As[akb + 1][arow] = av.y;
        As[akb + 2][arow] = av.z; As[akb + 3][arow] = av.w;
        float4 bv = *reinterpret_cast<const float4*>(W + (size_t)(k0 + bkr) * D_ + nbase + bnb);
        *reinterpret_cast<float4*>(&Bs[bkr][bnb]) = bv;
        __syncthreads();
#pragma unroll
        for (int kk = 0; kk < 8; kk++) {
            float ra[8], rb[8];
#pragma unroll
            for (int i = 0; i < 8; i++) ra[i] = As[kk][ty * 8 + i];
#pragma unroll
            for (int j = 0; j < 8; j++) rb[j] = Bs[kk][tx * 8 + j];
#pragma unroll
            for (int i = 0; i < 8; i++)
#pragma unroll
                for (int j = 0; j < 8; j++)
                    acc[i][j] = fmaf(ra[i], rb[j], acc[i][j]);
        }
        __syncthreads();
    }

    float* Chi = z ? g_khi : g_qhi;
    float* Clo = z ? g_klo : g_qlo;
    const int m0 = blockIdx.y * 128 + ty * 8;
    const int n0 = nbase + tx * 8;
#pragma unroll
    for (int i = 0; i < 8; i++)
#pragma unroll
        for (int j = 0; j < 8; j++) {
            float v = acc[i][j] + bias[n0 + j];
            float hf = rna(v);
            Chi[(size_t)(m0 + i) * D_ + n0 + j] = hf;
            Clo[(size_t)(m0 + i) * D_ + n0 + j] = rna(v - hf);
        }
}

// ---------------------------------------------------------------------------
// z-score attention (bit-packed adj, stores rna-rounded weights)
// ---------------------------------------------------------------------------
__device__ __forceinline__ float blockReduceSum(float v, float* sbuf) {
    const int tid = threadIdx.x;
#pragma unroll
    for (int o = 16; o > 0; o >>= 1) v += __shfl_xor_sync(0xffffffffu, v, o);
    if ((tid & 31) == 0) sbuf[tid >> 5] = v;
    __syncthreads();
    if (tid < 8) {
        v = sbuf[tid];
#pragma unroll
        for (int o = 4; o > 0; o >>= 1) v += __shfl_xor_sync(0xffu, v, o);
        if (tid == 0) sbuf[0] = v;
    }
    __syncthreads();
    float r = sbuf[0];
    __syncthreads();
    return r;
}
__device__ __forceinline__ float blockReduceMax(float v, float* sbuf) {
    const int tid = threadIdx.x;
#pragma unroll
    for (int o = 16; o > 0; o >>= 1) v = fmaxf(v, __shfl_xor_sync(0xffffffffu, v, o));
    if ((tid & 31) == 0) sbuf[tid >> 5] = v;
    __syncthreads();
    if (tid < 8) {
        v = sbuf[tid];
#pragma unroll
        for (int o = 4; o > 0; o >>= 1) v = fmaxf(v, __shfl_xor_sync(0xffu, v, o));
        if (tid == 0) sbuf[0] = v;
    }
    __syncthreads();
    float r = sbuf[0];
    __syncthreads();
    return r;
}

__global__ __launch_bounds__(256) void zscore_kernel(const int* __restrict__ mask) {
    const int row = blockIdx.x;
    const int i  = row & (N_ - 1);
    const int bh = row >> 10;
    const int b  = bh >> 2;
    float* sc = g_attn + (size_t)row * N_;
    const uint32_t* abits = g_adjbits + ((size_t)b * N_ + i) * (N_ / 32);
    const int* mrow = mask + (size_t)b * N_;
    const int tid = threadIdx.x;
    __shared__ float sbuf[8];

    float v[4], av[4];
    int mv[4];
    float cnt = 0.f, s = 0.f;
#pragma unroll
    for (int e = 0; e < 4; e++) {
        int j = tid + e * 256;
        v[e] = sc[j];
        mv[e] = (mrow[j] == 0);
        av[e] = (float)((abits[j >> 5] >> (j & 31)) & 1u);
        if (mv[e]) { cnt += 1.f; s += v[e]; }
    }
    cnt = blockReduceSum(cnt, sbuf);
    s   = blockReduceSum(s, sbuf);
    const float mean = s / (cnt + 1e-4f);

    float ss = 0.f;
#pragma unroll
    for (int e = 0; e < 4; e++) {
        float d = v[e] - mean;
        if (mv[e]) ss += d * d;
    }
    ss = blockReduceSum(ss, sbuf);
    const float stdv = sqrtf(ss / (cnt + 1e-4f) + 1e-10f);

    float s2[4];
    int keep[4];
#pragma unroll
    for (int e = 0; e < 4; e++) {
        float z = (v[e] - mean) / (stdv + 1e-4f);
        if (!mv[e]) z = 0.f;
        int th = (z < 0.f);
        s2[e] = (th || !mv[e]) ? -1e9f : z;
        keep[e] = (mv[e] && !th && (av[e] != 0.f));
    }
    float mx = -1e30f;
#pragma unroll
    for (int e = 0; e < 4; e++) mx = fmaxf(mx, s2[e]);
    mx = blockReduceMax(mx, sbuf);

    float ev[4], se = 0.f;
#pragma unroll
    for (int e = 0; e < 4; e++) {
        float ee = mv[e] ? (expf(s2[e] - mx) * av[e]) : 0.f;
        ee += 1e-10f;
        ev[e] = ee;
        se += ee;
    }
    se = blockReduceSum(se, sbuf);

    float dsum = 0.f;
#pragma unroll
    for (int e = 0; e < 4; e++) {
        int j = tid + e * 256;
        float w = keep[e] ? (ev[e] / se) : 0.f;
        sc[j] = rna(w);
        dsum += w;
    }
    dsum = blockReduceSum(dsum, sbuf);
    if (tid == 0) g_denom[row] = dsum + 1.f;
}

// ===========================================================================
extern "C" void kernel_launch(void* const* d_in, const int* in_sizes, int n_in,
                              void* d_out, int out_size) {
    const float* gcn   = (const float*)d_in[0];
    const float* rel   = (const float*)d_in[1];
    const int*   adj   = (const int*)d_in[2];
    const int*   mask  = (const int*)d_in[3];
    const float* W_Q   = (const float*)d_in[4];
    const float* b_Q   = (const float*)d_in[5];
    const float* W_K   = (const float*)d_in[6];
    const float* b_K   = (const float*)d_in[7];
    const float* W_gcn = (const float*)d_in[8];
    const float* b_gcn = (const float*)d_in[9];
    const float* W_out = (const float*)d_in[10];
    const float* b_out = (const float*)d_in[11];
    float* out = (float*)d_out;

    cudaFuncSetAttribute(axpx_mma,    cudaFuncAttributeMaxDynamicSharedMemorySize, MMA_SMEM);
    cudaFuncSetAttribute(tw_mma,      cudaFuncAttributeMaxDynamicSharedMemorySize, MMA_SMEM);
    cudaFuncSetAttribute(final_mma,   cudaFuncAttributeMaxDynamicSharedMemorySize, MMA_SMEM);
    cudaFuncSetAttribute(scores3_mma, cudaFuncAttributeMaxDynamicSharedMemorySize, SC_SMEM);

    float* gcnr_p; cudaGetSymbolAddress((void**)&gcnr_p, g_gcnr);
    float* wgr_p;  cudaGetSymbolAddress((void**)&wgr_p,  g_wgr);
    float* wor_p;  cudaGetSymbolAddress((void**)&wor_p,  g_wor);

    // Prep: rounded operand copies + adj bit-pack
    round_copy<<<BN_ * D_ / 1024, 256>>>(gcn, gcnr_p);
    round_copy<<<8 * D_ * D_ / 1024, 256>>>(W_gcn, wgr_p);
    round_copy<<<FD_ * D_ / 1024, 256>>>(W_out, wor_p);
    pack_adj<<<B_ * N_ * N_ / 256, 256>>>(adj);

    // q/k projections (fp32 FFMA) -> tf32 hi/lo
    proj_kernel<<<dim3(2, 32, 2), 256>>>(gcn, rel, W_Q, b_Q, W_K, b_K);

    // scores (3xTF32, fp32-accurate) + z-score attention
    scores3_mma<<<dim3(8, 8, 16), 256, SC_SMEM>>>();
    zscore_kernel<<<16 * N_, 256>>>(mask);

    // GCN layers (512-thread tf32 mma, single wave)
    for (int l = 0; l < L_; l++) {
        axpx_mma<<<dim3(8, 16), 512, MMA_SMEM>>>(gcn, l);
        tw_mma<<<dim3(8, 16), 512, MMA_SMEM>>>(b_gcn, l);
    }

    // output projection: split-K partials + deterministic reduce
    final_mma<<<dim3(4, 32), 512, MMA_SMEM>>>();
    reduce_final<<<1024, 256>>>(gcn, b_out, out);
}